// round 6
// baseline (speedup 1.0000x reference)
#include <cuda_runtime.h>
#include <cuda_bf16.h>
#include <cstdint>
#include <cfloat>

#define B_  16384
#define TD_ 4096
#define L_  1024
#define K_  8192
#define O_  128

#define MARGIN   1.5e-3f
#define CAND_MAX 16

// ---------------- scratch (device globals) -----------------------------------
__device__ float  g_ze[(size_t)B_ * L_];            // 64 MB
__device__ float  g_dt[(size_t)B_ * K_];            // 512 MB approx distances
__device__ __nv_bfloat16 g_zeb[(size_t)B_ * L_];    // 32 MB
__device__ __nv_bfloat16 g_cbb[(size_t)K_ * L_];    // 16 MB
__device__ __nv_bfloat16 g_qb[(size_t)B_ * L_];     // 32 MB
__device__ __nv_bfloat16 g_wclsb[(size_t)O_ * L_];
__device__ float  g_P[B_];
__device__ float  g_c[K_];
__device__ int    g_idx[B_];
__device__ int    g_cand2[(size_t)B_ * CAND_MAX];
__device__ int    g_ncand[B_];
__device__ double g_rowloss[B_];

// ---------------- helpers -----------------------------------------------------
__device__ __forceinline__ uint32_t smem_u32(const void* p) {
    uint32_t a;
    asm("{ .reg .u64 t; cvta.to.shared.u64 t, %1; cvt.u32.u64 %0, t; }"
        : "=r"(a) : "l"(p));
    return a;
}
__device__ __forceinline__ void cp16(uint32_t dst, const void* src) {
    asm volatile("cp.async.cg.shared.global [%0], [%1], 16;"
                 :: "r"(dst), "l"(src));
}
#define CP_COMMIT() asm volatile("cp.async.commit_group;" ::: "memory")
#define CP_WAIT1()  asm volatile("cp.async.wait_group 1;" ::: "memory")
#define CP_WAIT0()  asm volatile("cp.async.wait_group 0;" ::: "memory")

__device__ __forceinline__ void mma16816(float* c, uint32_t a0, uint32_t a1,
                                         uint32_t a2, uint32_t a3,
                                         uint32_t b0, uint32_t b1) {
    asm volatile(
        "mma.sync.aligned.m16n8k16.row.col.f32.bf16.bf16.f32 "
        "{%0,%1,%2,%3}, {%4,%5,%6,%7}, {%8,%9}, {%0,%1,%2,%3};"
        : "+f"(c[0]), "+f"(c[1]), "+f"(c[2]), "+f"(c[3])
        : "r"(a0), "r"(a1), "r"(a2), "r"(a3), "r"(b0), "r"(b1));
}

// smem tile: 128 rows x 64 bf16, padded to 144B/row (conflict-free LDS)
#define TROW 144
#define TSZ  (128 * TROW)
#define SM_GEMM (4 * TSZ)          // A0 A1 B0 B1

__device__ __forceinline__ void load_tile_cp(uint32_t dst, const __nv_bfloat16* src,
                                             int row0, int kc, int tid) {
    int r = tid >> 1, seg = tid & 1;
    const char* s = (const char*)(src + (size_t)(row0 + r) * L_ + kc + seg * 32);
    uint32_t d = dst + r * TROW + seg * 64;
    #pragma unroll
    for (int j = 0; j < 4; j++) cp16(d + j * 16, s + j * 16);
}

__device__ __forceinline__ void load_tile_reg(char* dst, const __nv_bfloat16* src,
                                              int row0, int Kd, int kc, int tid) {
    int r = tid >> 1, seg = tid & 1;
    const uint4* s = (const uint4*)(src + (size_t)(row0 + r) * Kd + kc + seg * 32);
    uint4* d = (uint4*)(dst + r * TROW + seg * 64);
    d[0] = s[0]; d[1] = s[1]; d[2] = s[2]; d[3] = s[3];
}

__device__ __forceinline__ void mma_chunk(const char* smA, const char* smB,
                                          int wm, int wn, int g, int tig,
                                          float acc[2][8][4]) {
    #pragma unroll
    for (int kk = 0; kk < 4; kk++) {
        uint32_t a[2][4];
        #pragma unroll
        for (int m2 = 0; m2 < 2; m2++) {
            int r0 = wm * 32 + m2 * 16 + g;
            int cb0 = (kk * 16 + 2 * tig) * 2;
            a[m2][0] = *(const uint32_t*)(smA + r0 * TROW + cb0);
            a[m2][1] = *(const uint32_t*)(smA + (r0 + 8) * TROW + cb0);
            a[m2][2] = *(const uint32_t*)(smA + r0 * TROW + cb0 + 16);
            a[m2][3] = *(const uint32_t*)(smA + (r0 + 8) * TROW + cb0 + 16);
        }
        #pragma unroll
        for (int n = 0; n < 8; n++) {
            int cn = wn * 64 + n * 8 + g;
            int cb0 = (kk * 16 + 2 * tig) * 2;
            uint32_t b0 = *(const uint32_t*)(smB + cn * TROW + cb0);
            uint32_t b1 = *(const uint32_t*)(smB + cn * TROW + cb0 + 16);
            mma16816(acc[0][n], a[0][0], a[0][1], a[0][2], a[0][3], b0, b1);
            mma16816(acc[1][n], a[1][0], a[1][1], a[1][2], a[1][3], b0, b1);
        }
    }
}

// ================= dist GEMM: g_dt = P - 2*(zeb @ cbb^T) + c =================
__global__ __launch_bounds__(256) void dist_gemm_kernel(void)
{
    extern __shared__ char sm[];
    uint32_t sb = smem_u32(sm);
    char* bufA[2] = { sm, sm + TSZ };
    char* bufB[2] = { sm + 2 * TSZ, sm + 3 * TSZ };
    uint32_t sA[2] = { sb, sb + TSZ };
    uint32_t sB[2] = { sb + 2 * TSZ, sb + 3 * TSZ };

    int tid = threadIdx.x, w = tid >> 5, lane = tid & 31;
    int wm = w & 3, wn = w >> 2;
    int g = lane >> 2, tig = lane & 3;
    int bm = blockIdx.y * 128, bn = blockIdx.x * 128;

    float acc[2][8][4];
    #pragma unroll
    for (int m2 = 0; m2 < 2; m2++)
        #pragma unroll
        for (int n = 0; n < 8; n++)
            #pragma unroll
            for (int q = 0; q < 4; q++) acc[m2][n][q] = 0.0f;

    // prologue: stage 0 and 1 in flight
    load_tile_cp(sA[0], g_zeb, bm, 0, tid);
    load_tile_cp(sB[0], g_cbb, bn, 0, tid);
    CP_COMMIT();
    load_tile_cp(sA[1], g_zeb, bm, 64, tid);
    load_tile_cp(sB[1], g_cbb, bn, 64, tid);
    CP_COMMIT();

    for (int c = 0; c < 16; c++) {
        if (c < 15) CP_WAIT1(); else CP_WAIT0();
        __syncthreads();
        mma_chunk(bufA[c & 1], bufB[c & 1], wm, wn, g, tig, acc);
        __syncthreads();
        if (c + 2 < 16) {
            int kc = (c + 2) * 64, st = c & 1;
            load_tile_cp(sA[st], g_zeb, bm, kc, tid);
            load_tile_cp(sB[st], g_cbb, bn, kc, tid);
            CP_COMMIT();
        }
    }

    float Pr[4];
    #pragma unroll
    for (int ri = 0; ri < 4; ri++) Pr[ri] = __ldg(&g_P[bm + wm * 32 + ri * 8 + g]);

    #pragma unroll
    for (int m2 = 0; m2 < 2; m2++)
        #pragma unroll
        for (int q = 0; q < 4; q++) {
            int ri = m2 * 2 + (q >> 1);
            int row = bm + wm * 32 + ri * 8 + g;
            float* drow = g_dt + (size_t)row * K_ + bn;
            #pragma unroll
            for (int n = 0; n < 8; n++) {
                int cl = wn * 64 + n * 8 + 2 * tig + (q & 1);
                float t = Pr[ri] - 2.0f * acc[m2][n][q];
                drow[cl] = t + __ldg(&g_c[bn + cl]);
            }
        }
}

// ================= per-row min + candidate collection ========================
__global__ void scan_kernel(void)
{
    int w = threadIdx.x >> 5, lane = threadIdx.x & 31;
    int row = blockIdx.x * 8 + w;
    const float* d = g_dt + (size_t)row * K_;

    float m = FLT_MAX;
    for (int j = lane * 4; j < K_; j += 128) {
        float4 v = *(const float4*)(d + j);
        m = fminf(m, fminf(fminf(v.x, v.y), fminf(v.z, v.w)));
    }
    #pragma unroll
    for (int o = 16; o > 0; o >>= 1) m = fminf(m, __shfl_xor_sync(0xffffffffu, m, o));

    float thr = m + MARGIN;
    int cnt = 0;
    for (int j0 = 0; j0 < K_; j0 += 128) {
        float4 v = *(const float4*)(d + j0 + lane * 4);
        float dv[4] = { v.x, v.y, v.z, v.w };
        #pragma unroll
        for (int e = 0; e < 4; e++) {
            unsigned mask = __ballot_sync(0xffffffffu, dv[e] < thr);
            if (dv[e] < thr) {
                int slot = cnt + __popc(mask & ((1u << lane) - 1u));
                if (slot < CAND_MAX)
                    g_cand2[(size_t)row * CAND_MAX + slot] = j0 + lane * 4 + e;
            }
            cnt += __popc(mask);
        }
    }
    if (lane == 0) g_ncand[row] = cnt;
}

// ================= exact refinement (proven sequential-fp32 chain) ===========
__global__ void refine_kernel(const float* __restrict__ cb,
                              float* __restrict__ out_idx_f, int write_idx)
{
    int w = threadIdx.x >> 5, lane = threadIdx.x & 31;
    int row = blockIdx.x * 8 + w;
    const float* ze = g_ze + (size_t)row * L_;
    float P = g_P[row];
    int cnt = g_ncand[row];

    float bd = FLT_MAX; int bi = 0x7FFFFFFF;
    if (cnt <= CAND_MAX) {
        if (lane < cnt) {
            int col = g_cand2[(size_t)row * CAND_MAX + lane];
            const float* e = cb + (size_t)col * L_;
            float s = 0.0f;
            #pragma unroll 4
            for (int k = 0; k < L_; k++) s = fmaf(__ldg(&ze[k]), __ldg(&e[k]), s);
            float t = P - 2.0f * s;
            bd = t + __ldg(&g_c[col]);
            bi = col;
        }
    } else {
        for (int col = lane; col < K_; col += 32) {
            const float* e = cb + (size_t)col * L_;
            float s = 0.0f;
            #pragma unroll 4
            for (int k = 0; k < L_; k++) s = fmaf(__ldg(&ze[k]), __ldg(&e[k]), s);
            float t = P - 2.0f * s;
            float dv = t + __ldg(&g_c[col]);
            if (dv < bd || (dv == bd && col < bi)) { bd = dv; bi = col; }
        }
    }
    #pragma unroll
    for (int o = 16; o > 0; o >>= 1) {
        float od = __shfl_xor_sync(0xffffffffu, bd, o);
        int oi = __shfl_xor_sync(0xffffffffu, bi, o);
        if (od < bd || (od == bd && oi < bi)) { bd = od; bi = oi; }
    }
    if (lane == 0) {
        g_idx[row] = bi;
        if (write_idx) out_idx_f[row] = (float)bi;
    }
}

// ================= classifier GEMM (bf16 HMMA, proven) =======================
__global__ __launch_bounds__(256) void cls_mma_kernel(
    const __nv_bfloat16* __restrict__ A, const __nv_bfloat16* __restrict__ Bm,
    const float* __restrict__ bias, float* __restrict__ C, int N)
{
    extern __shared__ char sm[];
    char* A0 = sm;            char* A1 = sm + TSZ;
    char* B0 = sm + 2 * TSZ;  char* B1 = sm + 3 * TSZ;

    int tid = threadIdx.x, w = tid >> 5, lane = tid & 31;
    int wm = w & 3, wn = w >> 2;
    int g = lane >> 2, tig = lane & 3;
    int bm = blockIdx.y * 128, bn = blockIdx.x * 128;

    float acc[2][8][4];
    #pragma unroll
    for (int m2 = 0; m2 < 2; m2++)
        #pragma unroll
        for (int n = 0; n < 8; n++)
            #pragma unroll
            for (int q = 0; q < 4; q++) acc[m2][n][q] = 0.0f;

    load_tile_reg(A0, A, bm, L_, 0, tid);
    load_tile_reg(B0, Bm, bn, L_, 0, tid);
    __syncthreads();
    for (int c = 0; c < 16; c++) {
        if (c + 1 < 16) {
            char* an = (c & 1) ? A0 : A1;
            char* bn2 = (c & 1) ? B0 : B1;
            load_tile_reg(an, A, bm, L_, (c + 1) * 64, tid);
            load_tile_reg(bn2, Bm, bn, L_, (c + 1) * 64, tid);
        }
        mma_chunk((c & 1) ? A1 : A0, (c & 1) ? B1 : B0, wm, wn, g, tig, acc);
        __syncthreads();
    }

    #pragma unroll
    for (int m2 = 0; m2 < 2; m2++)
        #pragma unroll
        for (int q = 0; q < 4; q++) {
            int row = bm + wm * 32 + m2 * 16 + (q >> 1) * 8 + g;
            #pragma unroll
            for (int n = 0; n < 8; n++) {
                int col = bn + wn * 64 + n * 8 + 2 * tig + (q & 1);
                C[(size_t)row * N + col] = acc[m2][n][q] + __ldg(&bias[col]);
            }
        }
}

// ================= proven fp32 z_e SGEMM =====================================
__global__ __launch_bounds__(256) void sgemm_nt_bias(
    const float* __restrict__ A, const float* __restrict__ Bm,
    const float* __restrict__ bias, float* __restrict__ C,
    int M, int N, int Kd)
{
    const int BK = 8;
    __shared__ float As[BK][128];
    __shared__ float Bs[BK][128];
    int bm = blockIdx.y * 128, bn = blockIdx.x * 128;
    int tid = threadIdx.x;
    int tx = tid & 15, ty = tid >> 4;
    int lrow = tid >> 1, lcol = (tid & 1) * 4;
    const float* Aptr = A  + (size_t)(bm + lrow) * Kd + lcol;
    const float* Bptr = Bm + (size_t)(bn + lrow) * Kd + lcol;
    float acc[8][8];
    #pragma unroll
    for (int i = 0; i < 8; i++)
        #pragma unroll
        for (int j = 0; j < 8; j++) acc[i][j] = 0.0f;
    for (int k0 = 0; k0 < Kd; k0 += BK) {
        float4 av = *(const float4*)(Aptr + k0);
        float4 bv = *(const float4*)(Bptr + k0);
        As[lcol + 0][lrow] = av.x; As[lcol + 1][lrow] = av.y;
        As[lcol + 2][lrow] = av.z; As[lcol + 3][lrow] = av.w;
        Bs[lcol + 0][lrow] = bv.x; Bs[lcol + 1][lrow] = bv.y;
        Bs[lcol + 2][lrow] = bv.z; Bs[lcol + 3][lrow] = bv.w;
        __syncthreads();
        #pragma unroll
        for (int kk = 0; kk < BK; kk++) {
            float ar[8], br[8];
            #pragma unroll
            for (int i = 0; i < 8; i++) ar[i] = As[kk][ty * 8 + i];
            #pragma unroll
            for (int j = 0; j < 8; j++) br[j] = Bs[kk][tx * 8 + j];
            #pragma unroll
            for (int i = 0; i < 8; i++)
                #pragma unroll
                for (int j = 0; j < 8; j++)
                    acc[i][j] = fmaf(ar[i], br[j], acc[i][j]);
        }
        __syncthreads();
    }
    #pragma unroll
    for (int i = 0; i < 8; i++) {
        int r = bm + ty * 8 + i;
        #pragma unroll
        for (int j = 0; j < 8; j += 4) {
            int c = bn + tx * 8 + j;
            float4 o;
            o.x = acc[i][j + 0] + bias[c + 0];
            o.y = acc[i][j + 1] + bias[c + 1];
            o.z = acc[i][j + 2] + bias[c + 2];
            o.w = acc[i][j + 3] + bias[c + 3];
            *(float4*)&C[(size_t)r * N + c] = o;
        }
    }
}

// ================= small kernels =============================================
__global__ void rowsumsq_kernel(const float* __restrict__ src, float* __restrict__ dst,
                                int rows, int cols)
{
    int row  = blockIdx.x * (blockDim.x >> 5) + (threadIdx.x >> 5);
    int lane = threadIdx.x & 31;
    if (row >= rows) return;
    const float* r = src + (size_t)row * cols;
    double s = 0.0;
    for (int j = lane; j < cols; j += 32) {
        float v = r[j];
        s += (double)v * (double)v;
    }
    #pragma unroll
    for (int o = 16; o > 0; o >>= 1) s += __shfl_down_sync(0xffffffffu, s, o);
    if (lane == 0) dst[row] = (float)s;
}

__global__ void f2bf_kernel(const float* __restrict__ x, __nv_bfloat16* y, size_t n)
{
    size_t i = (size_t)blockIdx.x * blockDim.x + threadIdx.x;
    if (i < n) y[i] = __float2bfloat16(x[i]);
}

__global__ void gather_qb_kernel(const float* __restrict__ cb)
{
    size_t i = (size_t)blockIdx.x * blockDim.x + threadIdx.x;
    int row = (int)(i >> 10);
    int col = (int)(i & 1023);
    g_qb[i] = __float2bfloat16(cb[(size_t)g_idx[row] * L_ + col]);
}

__global__ void loss_kernel(const float* __restrict__ cb)
{
    int row = blockIdx.x;
    const float* ze = g_ze + (size_t)row * L_;
    const float* q  = cb   + (size_t)g_idx[row] * L_;
    double s = 0.0;
    for (int j = threadIdx.x; j < L_; j += blockDim.x) {
        float dlt = q[j] - ze[j];
        s += (double)dlt * (double)dlt;
    }
    __shared__ double sh[256];
    sh[threadIdx.x] = s;
    __syncthreads();
    for (int o = 128; o > 0; o >>= 1) {
        if (threadIdx.x < o) sh[threadIdx.x] += sh[threadIdx.x + o];
        __syncthreads();
    }
    if (threadIdx.x == 0) g_rowloss[row] = sh[0];
}

__global__ void loss_reduce_kernel(float* __restrict__ out_loss)
{
    __shared__ double sh[256];
    double s = 0.0;
    for (int r = threadIdx.x; r < B_; r += 256) s += g_rowloss[r];
    sh[threadIdx.x] = s;
    __syncthreads();
    for (int o = 128; o > 0; o >>= 1) {
        if (threadIdx.x < o) sh[threadIdx.x] += sh[threadIdx.x + o];
        __syncthreads();
    }
    if (threadIdx.x == 0) {
        float m = (float)(sh[0] / ((double)B_ * (double)L_));
        out_loss[0] = m + 0.25f * m;
    }
}

__global__ void softmax_kernel(float* __restrict__ logits)
{
    int row = blockIdx.x;
    float* p = logits + (size_t)row * O_;
    float v = p[threadIdx.x];
    __shared__ float shm[4];
    float m = v;
    #pragma unroll
    for (int o = 16; o > 0; o >>= 1) m = fmaxf(m, __shfl_xor_sync(0xffffffffu, m, o));
    if ((threadIdx.x & 31) == 0) shm[threadIdx.x >> 5] = m;
    __syncthreads();
    float mm = fmaxf(fmaxf(shm[0], shm[1]), fmaxf(shm[2], shm[3]));
    __syncthreads();
    float e = expf(v - mm);
    float s = e;
    #pragma unroll
    for (int o = 16; o > 0; o >>= 1) s += __shfl_xor_sync(0xffffffffu, s, o);
    if ((threadIdx.x & 31) == 0) shm[threadIdx.x >> 5] = s;
    __syncthreads();
    float ss = shm[0] + shm[1] + shm[2] + shm[3];
    p[threadIdx.x] = e / ss;
}

// ================= launch =====================================================
extern "C" void kernel_launch(void* const* d_in, const int* in_sizes, int n_in,
                              void* d_out, int out_size)
{
    const float* x     = (const float*)d_in[0];
    const float* W_enc = (const float*)d_in[1];
    const float* b_enc = (const float*)d_in[2];
    const float* cb    = (const float*)d_in[3];
    const float* W_cls = (const float*)d_in[4];
    const float* b_cls = (const float*)d_in[5];
    float* out = (float*)d_out;

    float* out_logits = out;
    float* out_loss   = out + (size_t)B_ * O_;
    float* out_idx    = out + (size_t)B_ * O_ + 1;
    int has_loss = (out_size >= B_ * O_ + 1);
    int has_idx  = (out_size >= B_ * O_ + 1 + B_);

    cudaFuncSetAttribute(dist_gemm_kernel, cudaFuncAttributeMaxDynamicSharedMemorySize, SM_GEMM);
    cudaFuncSetAttribute(cls_mma_kernel, cudaFuncAttributeMaxDynamicSharedMemorySize, SM_GEMM);

    void *p;
    float *ze, *Pv, *cv;
    __nv_bfloat16 *zeb, *cbb, *qb, *wclsb;
    cudaGetSymbolAddress(&p, g_ze);    ze    = (float*)p;
    cudaGetSymbolAddress(&p, g_P);     Pv    = (float*)p;
    cudaGetSymbolAddress(&p, g_c);     cv    = (float*)p;
    cudaGetSymbolAddress(&p, g_zeb);   zeb   = (__nv_bfloat16*)p;
    cudaGetSymbolAddress(&p, g_cbb);   cbb   = (__nv_bfloat16*)p;
    cudaGetSymbolAddress(&p, g_qb);    qb    = (__nv_bfloat16*)p;
    cudaGetSymbolAddress(&p, g_wclsb); wclsb = (__nv_bfloat16*)p;

    // codebook norms + bf16 conversions
    rowsumsq_kernel<<<K_ / 8, 256>>>(cb, cv, K_, L_);
    f2bf_kernel<<<(unsigned)((size_t)K_ * L_ / 256), 256>>>(cb, cbb, (size_t)K_ * L_);
    f2bf_kernel<<<(unsigned)((size_t)O_ * L_ / 256), 256>>>(W_cls, wclsb, (size_t)O_ * L_);

    // z_e: sequential-k fp32 SGEMM (proven)
    {
        dim3 grid(L_ / 128, B_ / 128);
        sgemm_nt_bias<<<grid, 256>>>(x, W_enc, b_enc, ze, B_, L_, TD_);
    }
    rowsumsq_kernel<<<B_ / 8, 256>>>(ze, Pv, B_, L_);
    f2bf_kernel<<<(unsigned)((size_t)B_ * L_ / 256), 256>>>(ze, zeb, (size_t)B_ * L_);

    // distances: lean bf16 HMMA GEMM -> d~ buffer -> scan -> exact refine
    {
        dim3 grid(K_ / 128, B_ / 128);
        dist_gemm_kernel<<<grid, 256, SM_GEMM>>>();
    }
    scan_kernel<<<B_ / 8, 256>>>();
    refine_kernel<<<B_ / 8, 256>>>(cb, out_idx, has_idx);

    // loss
    loss_kernel<<<B_, 256>>>(cb);
    if (has_loss) loss_reduce_kernel<<<1, 256>>>(out_loss);

    // classifier on gathered codebook rows + softmax
    gather_qb_kernel<<<(unsigned)((size_t)B_ * L_ / 256), 256>>>(cb);
    {
        dim3 grid(O_ / 128, B_ / 128);
        cls_mma_kernel<<<grid, 256, SM_GEMM>>>(qb, wclsb, b_cls, out_logits, O_);
    }
    softmax_kernel<<<B_, 128>>>(out_logits);
}